// round 10
// baseline (speedup 1.0000x reference)
#include <cuda_runtime.h>
#include <math.h>

#define NN    50000
#define FI    20
#define HIDD  500
#define NOUT  2
#define NPAIR 210            // upper-triangular (incl. diag) pairs of 20
#define BN_EPS 1e-5f
#define CH    250            // nodes per block in gather/stats (200 blocks)
#define NB    (NN / CH)
#define PAD   64             // padded-CSR width (deg ~ Poisson(16))
#define OVFC  4096           // overflow capacity (general-correctness fallback)

// ---- scratch (__device__ globals, zero-initialized; self-cleaning) ----
static __device__ int            g_cnt[NN];        // degree counter (build), zeroed in gather
static __device__ unsigned short g_slots[PAD * NN];// slot-major CSR: slots[j*NN+c]=row
static __device__ int            g_ovfn;           // overflow count (zeroed in k_prep)
static __device__ int2           g_ovf[OVFC];      // overflow (row,col) pairs
static __device__ float          g_dinv[NN];
static __device__ float4         g_Xs4[NN * 5];    // Xs = dinv[n] * X[n]
static __device__ float4         g_agg4[NN * 5];   // aggX = dinv * (sum + Xs)
static __device__ double         g_m[FI];          // column sums of aggX
static __device__ double         g_G[NPAIR];       // upper-tri Gram aggX^T aggX
static __device__ float          g_M2[FI * NOUT];  // folded 20x2 head matrix
static __device__ float          g_C[NOUT];        // folded bias

// K1: build padded CSR: for edge (r,c): slots[pos][c] = r  (int atomics only)
__global__ void __launch_bounds__(256) k_build(const int* __restrict__ ei, int E) {
    int t = blockIdx.x * blockDim.x + threadIdx.x;
    int e = 4 * t;
    if (e + 3 < E) {
        int4 r4 = *(const int4*)(ei + e);
        int4 c4 = *(const int4*)(ei + E + e);
        int rr[4] = {r4.x, r4.y, r4.z, r4.w};
        int cc[4] = {c4.x, c4.y, c4.z, c4.w};
#pragma unroll
        for (int k = 0; k < 4; k++) {
            int pos = atomicAdd(&g_cnt[cc[k]], 1);
            if (pos < PAD) g_slots[pos * NN + cc[k]] = (unsigned short)rr[k];
            else {
                int o = atomicAdd(&g_ovfn, 1);
                if (o < OVFC) g_ovf[o] = make_int2(rr[k], cc[k]);
            }
        }
    } else {
        for (int k = e; k < E; k++) {
            int r = ei[k], c = ei[E + k];
            int pos = atomicAdd(&g_cnt[c], 1);
            if (pos < PAD) g_slots[pos * NN + c] = (unsigned short)r;
            else {
                int o = atomicAdd(&g_ovfn, 1);
                if (o < OVFC) g_ovf[o] = make_int2(r, c);
            }
        }
    }
}

// K2: dinv = rsqrt(deg+1); Xs[n] = dinv[n]*X[n]  (keeps g_cnt for gather)
__global__ void __launch_bounds__(256) k_prepX(const float* __restrict__ X) {
    int n = blockIdx.x * blockDim.x + threadIdx.x;
    if (n >= NN) return;
    float d = rsqrtf((float)(g_cnt[n] + 1));
    g_dinv[n] = d;
    const float4* xr = (const float4*)(X + n * FI);
#pragma unroll
    for (int k = 0; k < 5; k++) {
        float4 v = xr[k];
        v.x *= d; v.y *= d; v.z *= d; v.w *= d;
        g_Xs4[n * 5 + k] = v;
    }
}

// K3: gather (no float atomics) + finalize aggX + stats. Self-cleans g_cnt.
__global__ void __launch_bounds__(256) k_gather(float dummy) {
    __shared__ float s[CH * 21];               // stride 21: conflict-free
    int t = threadIdx.x;                       // 256 threads (250 gather)
    int n0 = blockIdx.x * CH;
    int ovfn = g_ovfn;                         // 0 on this input

    if (t < CH) {
        int n = n0 + t;
        int deg = g_cnt[n];
        g_cnt[n] = 0;                          // self-clean for next replay
        float4 a0 = make_float4(0.f,0.f,0.f,0.f), a1 = a0, a2 = a0, a3 = a0, a4 = a0;
        int m = deg < PAD ? deg : PAD;
        for (int j = 0; j < m; j++) {
            int r = (int)g_slots[j * NN + n];  // coalesced across threads
            const float4* xs = g_Xs4 + r * 5;
            float4 v0 = __ldg(xs + 0), v1 = __ldg(xs + 1), v2 = __ldg(xs + 2),
                   v3 = __ldg(xs + 3), v4 = __ldg(xs + 4);
            a0.x += v0.x; a0.y += v0.y; a0.z += v0.z; a0.w += v0.w;
            a1.x += v1.x; a1.y += v1.y; a1.z += v1.z; a1.w += v1.w;
            a2.x += v2.x; a2.y += v2.y; a2.z += v2.z; a2.w += v2.w;
            a3.x += v3.x; a3.y += v3.y; a3.z += v3.z; a3.w += v3.w;
            a4.x += v4.x; a4.y += v4.y; a4.z += v4.z; a4.w += v4.w;
        }
        if (ovfn > 0) {                        // rare general-correctness path
            int L = ovfn < OVFC ? ovfn : OVFC;
            for (int o = 0; o < L; o++) {
                int2 rc = g_ovf[o];
                if (rc.y == n) {
                    const float4* xs = g_Xs4 + rc.x * 5;
                    float4 v0 = xs[0], v1 = xs[1], v2 = xs[2], v3 = xs[3], v4 = xs[4];
                    a0.x += v0.x; a0.y += v0.y; a0.z += v0.z; a0.w += v0.w;
                    a1.x += v1.x; a1.y += v1.y; a1.z += v1.z; a1.w += v1.w;
                    a2.x += v2.x; a2.y += v2.y; a2.z += v2.z; a2.w += v2.w;
                    a3.x += v3.x; a3.y += v3.y; a3.z += v3.z; a3.w += v3.w;
                    a4.x += v4.x; a4.y += v4.y; a4.z += v4.z; a4.w += v4.w;
                }
            }
        }
        // self term + dinv scaling
        float d = g_dinv[n];
        const float4* xsn = g_Xs4 + n * 5;
        float4 w0 = xsn[0], w1 = xsn[1], w2 = xsn[2], w3 = xsn[3], w4 = xsn[4];
        a0.x = d*(a0.x+w0.x); a0.y = d*(a0.y+w0.y); a0.z = d*(a0.z+w0.z); a0.w = d*(a0.w+w0.w);
        a1.x = d*(a1.x+w1.x); a1.y = d*(a1.y+w1.y); a1.z = d*(a1.z+w1.z); a1.w = d*(a1.w+w1.w);
        a2.x = d*(a2.x+w2.x); a2.y = d*(a2.y+w2.y); a2.z = d*(a2.z+w2.z); a2.w = d*(a2.w+w2.w);
        a3.x = d*(a3.x+w3.x); a3.y = d*(a3.y+w3.y); a3.z = d*(a3.z+w3.z); a3.w = d*(a3.w+w3.w);
        a4.x = d*(a4.x+w4.x); a4.y = d*(a4.y+w4.y); a4.z = d*(a4.z+w4.z); a4.w = d*(a4.w+w4.w);
        // publish: global (for k_final) + shared (for stats)
        float4* ag = g_agg4 + n * 5;
        ag[0] = a0; ag[1] = a1; ag[2] = a2; ag[3] = a3; ag[4] = a4;
        float* sr = s + t * 21;
        sr[0]=a0.x; sr[1]=a0.y; sr[2]=a0.z; sr[3]=a0.w;
        sr[4]=a1.x; sr[5]=a1.y; sr[6]=a1.z; sr[7]=a1.w;
        sr[8]=a2.x; sr[9]=a2.y; sr[10]=a2.z; sr[11]=a2.w;
        sr[12]=a3.x; sr[13]=a3.y; sr[14]=a3.z; sr[15]=a3.w;
        sr[16]=a4.x; sr[17]=a4.y; sr[18]=a4.z; sr[19]=a4.w;
    }
    __syncthreads();

    // stats: fp32 partials, double-atomic combine
    if (t < FI) {
        float b0 = 0.f, b1 = 0.f;
        for (int n = 0; n < CH; n += 2) {
            b0 += s[n * 21 + t];
            b1 += s[(n + 1) * 21 + t];
        }
        atomicAdd(&g_m[t], (double)(b0 + b1));
    } else if (t < FI + NPAIR) {
        int p = t - FI, i = 0;
        while (p >= FI - i) { p -= FI - i; i++; }
        int j = i + p;
        float b0 = 0.f, b1 = 0.f;
        for (int n = 0; n < CH; n += 2) {
            b0 += s[n * 21 + i] * s[n * 21 + j];
            b1 += s[(n + 1) * 21 + i] * s[(n + 1) * 21 + j];
        }
        atomicAdd(&g_G[t - FI], (double)(b0 + b1));
    }
}

// K4 (1 block, 512 threads): fold BN into the head; emit rsu_embedding.
// ALL arrays the fold loops touch are staged into shared first — R8/R9's
// 26-27us came from serialized global LDG latency chains in these loops.
__global__ void __launch_bounds__(512) k_prep(
                       const float* __restrict__ W,      // gcn_W  [20,500]
                       const float* __restrict__ b,      // gcn_b  [500]
                       const float* __restrict__ gamma,  // [500]
                       const float* __restrict__ beta,   // [500]
                       const float* __restrict__ W2,     // lin_W  [500,2]
                       const float* __restrict__ lb,     // lin_b  [2]
                       float* __restrict__ out_rsu) {    // d_out + NN*NOUT
    __shared__ float  sW[FI * HIDD];       // 40 KB
    __shared__ float  sW2[HIDD * NOUT];    // 4 KB (staged lin_W)
    __shared__ float  sB[HIDD];            // 2 KB (staged gcn_b)
    __shared__ float  sS[HIDD], sT[HIDD];
    __shared__ double smm[FI];
    __shared__ float  sGfull[FI][FI + 1];  // full symmetric Gram, padded
    __shared__ float  sRed[42 * 8];
    int t = threadIdx.x;               // 512 threads
    for (int k = t; k < FI * HIDD; k += 512) sW[k] = W[k];
    for (int k = t; k < HIDD * NOUT; k += 512) sW2[k] = W2[k];
    if (t < HIDD)  sB[t] = b[t];
    if (t < FI)    { smm[t] = g_m[t];  g_m[t] = 0.0; }        // self-clean
    if (t < NPAIR) {                                           // expand + self-clean
        int p = t, i = 0;
        while (p >= FI - i) { p -= FI - i; i++; }
        int j = i + p;
        float v = (float)g_G[t];
        g_G[t] = 0.0;
        sGfull[i][j] = v;
        sGfull[j][i] = v;
    }
    if (t == 511) g_ovfn = 0;                                  // self-clean
    __syncthreads();

    const float* a0 = (const float*)g_agg4;   // node 0 row
    if (t < HIDD) {
        int f = t;
        float w[FI];
#pragma unroll
        for (int i = 0; i < FI; i++) w[i] = sW[i * HIDD + f];
        float bf = sB[f];
        double su = 0.0;
#pragma unroll
        for (int i = 0; i < FI; i++) su += smm[i] * (double)w[i];
        float suf = (float)su;
        float mean = (suf + (float)NN * bf) * (1.f / (float)NN);
        float q = 0.f;
#pragma unroll 2
        for (int i = 0; i < FI; i++) {
            float qi = 0.f;
#pragma unroll
            for (int j = 0; j < FI; j++) qi += sGfull[i][j] * w[j];
            q += qi * w[i];
        }
        float sumsq_over_n = q * (1.f / (float)NN)
                           + 2.f * bf * suf * (1.f / (float)NN) + bf * bf;
        float var = sumsq_over_n - mean * mean;
        float sc = gamma[f] * rsqrtf(var + BN_EPS);
        float tt = beta[f] - mean * sc;
        sS[f] = sc; sT[f] = tt;
        float u0 = 0.f;
#pragma unroll
        for (int i = 0; i < FI; i++) u0 += a0[i] * w[i];
        out_rsu[f] = (u0 + bf) * sc + tt;
    }
    __syncthreads();

    if (t < 42 * 8) {                     // parallel fold of M2/C (pure LDS now)
        int o = t / 8, part = t % 8;
        int f0 = part * 63;
        int f1 = (f0 + 63 < HIDD) ? f0 + 63 : HIDD;
        float acc = 0.f;
        if (o < FI * NOUT) {
            int i2 = o / NOUT, oo = o % NOUT;
            for (int f = f0; f < f1; f++)
                acc += sW[i2 * HIDD + f] * sS[f] * sW2[f * NOUT + oo];
        } else {
            int oo = o - FI * NOUT;
            for (int f = f0; f < f1; f++)
                acc += (sB[f] * sS[f] + sT[f]) * sW2[f * NOUT + oo];
        }
        sRed[t] = acc;
    }
    __syncthreads();
    if (t < 42) {
        float acc = 0.f;
#pragma unroll
        for (int k = 0; k < 8; k++) acc += sRed[t * 8 + k];
        if (t < FI * NOUT) g_M2[t] = acc;
        else               g_C[t - FI * NOUT] = acc + lb[t - FI * NOUT];
    }
}

// K5: per-node head: logits = relu(aggX[n].M2 + C); softmax over 2 classes
__global__ void __launch_bounds__(256) k_final(float* __restrict__ out) {
    __shared__ float sM[FI * NOUT];
    __shared__ float sC[NOUT];
    int t = threadIdx.x;
    if (t < FI * NOUT) sM[t] = g_M2[t];
    if (t < NOUT)      sC[t] = g_C[t];
    __syncthreads();
    int n = blockIdx.x * blockDim.x + t;
    if (n >= NN) return;
    float p0 = sC[0], p1 = sC[1];
    const float4* ar = (const float4*)(g_agg4 + n * 5);
#pragma unroll
    for (int k = 0; k < 5; k++) {
        float4 v = ar[k];
        p0 += v.x * sM[(4 * k + 0) * NOUT] + v.y * sM[(4 * k + 1) * NOUT]
            + v.z * sM[(4 * k + 2) * NOUT] + v.w * sM[(4 * k + 3) * NOUT];
        p1 += v.x * sM[(4 * k + 0) * NOUT + 1] + v.y * sM[(4 * k + 1) * NOUT + 1]
            + v.z * sM[(4 * k + 2) * NOUT + 1] + v.w * sM[(4 * k + 3) * NOUT + 1];
    }
    float l0 = fmaxf(p0, 0.f), l1 = fmaxf(p1, 0.f);
    float mx = fmaxf(l0, l1);
    float e0 = expf(l0 - mx), e1 = expf(l1 - mx);
    float inv = 1.f / (e0 + e1);
    out[2 * n + 0] = e0 * inv;
    out[2 * n + 1] = e1 * inv;
}

extern "C" void kernel_launch(void* const* d_in, const int* in_sizes, int n_in,
                              void* d_out, int out_size) {
    const float* X     = (const float*)d_in[0];   // node_feature [50000,20]
    const int*   ei    = (const int*)  d_in[1];   // edge_index   [2,E]
    const float* gcnW  = (const float*)d_in[2];   // [20,500]
    const float* gcnB  = (const float*)d_in[3];   // [500]
    const float* gamma = (const float*)d_in[4];   // [500]
    const float* beta  = (const float*)d_in[5];   // [500]
    const float* linW  = (const float*)d_in[6];   // [500,2]
    const float* linB  = (const float*)d_in[7];   // [2]
    float* out = (float*)d_out;                   // [NN*2 action_prob][500 rsu]

    int E = in_sizes[1] / 2;
    int nb  = (NN + 255) / 256;
    int eb4 = (E / 4 + 255) / 256 + 1;

    k_build<<<eb4, 256>>>(ei, E);
    k_prepX<<<nb, 256>>>(X);
    k_gather<<<NB, 256>>>(0.f);
    k_prep<<<1, 512>>>(gcnW, gcnB, gamma, beta, linW, linB, out + NN * NOUT);
    k_final<<<nb, 256>>>(out);
}

// round 11
// speedup vs baseline: 1.0595x; 1.0595x over previous
#include <cuda_runtime.h>
#include <math.h>

#define NN    50000
#define FI    20
#define HIDD  500
#define NOUT  2
#define NPAIR 210            // upper-triangular (incl. diag) pairs of 20
#define BN_EPS 1e-5f
#define CH    250            // nodes per block in gather/stats (200 blocks)
#define NB    (NN / CH)
#define NB2   196            // k_final blocks: 196*256 >= 50000
#define PAD   64             // padded-CSR width (deg ~ Poisson(16))
#define OVFC  4096           // overflow capacity (general-correctness fallback)

// ---- scratch (__device__ globals, zero-initialized; self-cleaning) ----
static __device__ int            g_cnt[NN];        // degree counter (build), zeroed in gather
static __device__ unsigned short g_slots[PAD * NN];// slot-major CSR: slots[j*NN+c]=row
static __device__ int            g_ovfn;           // overflow count (zeroed in k_final)
static __device__ int2           g_ovf[OVFC];      // overflow (row,col) pairs
static __device__ float          g_dinv[NN];
static __device__ float4         g_Xs4[NN * 5];    // Xs = dinv[n] * X[n]
static __device__ float4         g_agg4[NN * 5];   // aggX = dinv * (sum + Xs)
static __device__ double         g_m[FI];          // column sums of aggX
static __device__ double         g_G[NPAIR];       // upper-tri Gram aggX^T aggX
static __device__ int            g_c;              // k_final cleanup arrival counter

// K1: build padded CSR: for edge (r,c): slots[pos][c] = r  (int atomics only)
__global__ void __launch_bounds__(256) k_build(const int* __restrict__ ei, int E) {
    int t = blockIdx.x * blockDim.x + threadIdx.x;
    int e = 4 * t;
    if (e + 3 < E) {
        int4 r4 = *(const int4*)(ei + e);
        int4 c4 = *(const int4*)(ei + E + e);
        int rr[4] = {r4.x, r4.y, r4.z, r4.w};
        int cc[4] = {c4.x, c4.y, c4.z, c4.w};
#pragma unroll
        for (int k = 0; k < 4; k++) {
            int pos = atomicAdd(&g_cnt[cc[k]], 1);
            if (pos < PAD) g_slots[pos * NN + cc[k]] = (unsigned short)rr[k];
            else {
                int o = atomicAdd(&g_ovfn, 1);
                if (o < OVFC) g_ovf[o] = make_int2(rr[k], cc[k]);
            }
        }
    } else {
        for (int k = e; k < E; k++) {
            int r = ei[k], c = ei[E + k];
            int pos = atomicAdd(&g_cnt[c], 1);
            if (pos < PAD) g_slots[pos * NN + c] = (unsigned short)r;
            else {
                int o = atomicAdd(&g_ovfn, 1);
                if (o < OVFC) g_ovf[o] = make_int2(r, c);
            }
        }
    }
}

// K2: dinv = rsqrt(deg+1); Xs[n] = dinv[n]*X[n]  (keeps g_cnt for gather)
__global__ void __launch_bounds__(256) k_prepX(const float* __restrict__ X) {
    int n = blockIdx.x * blockDim.x + threadIdx.x;
    if (n >= NN) return;
    float d = rsqrtf((float)(g_cnt[n] + 1));
    g_dinv[n] = d;
    const float4* xr = (const float4*)(X + n * FI);
#pragma unroll
    for (int k = 0; k < 5; k++) {
        float4 v = xr[k];
        v.x *= d; v.y *= d; v.z *= d; v.w *= d;
        g_Xs4[n * 5 + k] = v;
    }
}

// K3: gather (no float atomics) + finalize aggX + stats. Self-cleans g_cnt.
__global__ void __launch_bounds__(256) k_gather(float dummy) {
    __shared__ float s[CH * 21];               // stride 21: conflict-free
    int t = threadIdx.x;                       // 256 threads (250 gather)
    int n0 = blockIdx.x * CH;
    int ovfn = g_ovfn;                         // 0 on this input

    if (t < CH) {
        int n = n0 + t;
        int deg = g_cnt[n];
        g_cnt[n] = 0;                          // self-clean for next replay
        float4 a0 = make_float4(0.f,0.f,0.f,0.f), a1 = a0, a2 = a0, a3 = a0, a4 = a0;
        int m = deg < PAD ? deg : PAD;
        for (int j = 0; j < m; j++) {
            int r = (int)g_slots[j * NN + n];  // coalesced across threads
            const float4* xs = g_Xs4 + r * 5;
            float4 v0 = __ldg(xs + 0), v1 = __ldg(xs + 1), v2 = __ldg(xs + 2),
                   v3 = __ldg(xs + 3), v4 = __ldg(xs + 4);
            a0.x += v0.x; a0.y += v0.y; a0.z += v0.z; a0.w += v0.w;
            a1.x += v1.x; a1.y += v1.y; a1.z += v1.z; a1.w += v1.w;
            a2.x += v2.x; a2.y += v2.y; a2.z += v2.z; a2.w += v2.w;
            a3.x += v3.x; a3.y += v3.y; a3.z += v3.z; a3.w += v3.w;
            a4.x += v4.x; a4.y += v4.y; a4.z += v4.z; a4.w += v4.w;
        }
        if (ovfn > 0) {                        // rare general-correctness path
            int L = ovfn < OVFC ? ovfn : OVFC;
            for (int o = 0; o < L; o++) {
                int2 rc = g_ovf[o];
                if (rc.y == n) {
                    const float4* xs = g_Xs4 + rc.x * 5;
                    float4 v0 = xs[0], v1 = xs[1], v2 = xs[2], v3 = xs[3], v4 = xs[4];
                    a0.x += v0.x; a0.y += v0.y; a0.z += v0.z; a0.w += v0.w;
                    a1.x += v1.x; a1.y += v1.y; a1.z += v1.z; a1.w += v1.w;
                    a2.x += v2.x; a2.y += v2.y; a2.z += v2.z; a2.w += v2.w;
                    a3.x += v3.x; a3.y += v3.y; a3.z += v3.z; a3.w += v3.w;
                    a4.x += v4.x; a4.y += v4.y; a4.z += v4.z; a4.w += v4.w;
                }
            }
        }
        // self term + dinv scaling
        float d = g_dinv[n];
        const float4* xsn = g_Xs4 + n * 5;
        float4 w0 = xsn[0], w1 = xsn[1], w2 = xsn[2], w3 = xsn[3], w4 = xsn[4];
        a0.x = d*(a0.x+w0.x); a0.y = d*(a0.y+w0.y); a0.z = d*(a0.z+w0.z); a0.w = d*(a0.w+w0.w);
        a1.x = d*(a1.x+w1.x); a1.y = d*(a1.y+w1.y); a1.z = d*(a1.z+w1.z); a1.w = d*(a1.w+w1.w);
        a2.x = d*(a2.x+w2.x); a2.y = d*(a2.y+w2.y); a2.z = d*(a2.z+w2.z); a2.w = d*(a2.w+w2.w);
        a3.x = d*(a3.x+w3.x); a3.y = d*(a3.y+w3.y); a3.z = d*(a3.z+w3.z); a3.w = d*(a3.w+w3.w);
        a4.x = d*(a4.x+w4.x); a4.y = d*(a4.y+w4.y); a4.z = d*(a4.z+w4.z); a4.w = d*(a4.w+w4.w);
        // publish: global (for k_final) + shared (for stats)
        float4* ag = g_agg4 + n * 5;
        ag[0] = a0; ag[1] = a1; ag[2] = a2; ag[3] = a3; ag[4] = a4;
        float* sr = s + t * 21;
        sr[0]=a0.x; sr[1]=a0.y; sr[2]=a0.z; sr[3]=a0.w;
        sr[4]=a1.x; sr[5]=a1.y; sr[6]=a1.z; sr[7]=a1.w;
        sr[8]=a2.x; sr[9]=a2.y; sr[10]=a2.z; sr[11]=a2.w;
        sr[12]=a3.x; sr[13]=a3.y; sr[14]=a3.z; sr[15]=a3.w;
        sr[16]=a4.x; sr[17]=a4.y; sr[18]=a4.z; sr[19]=a4.w;
    }
    __syncthreads();

    // stats: fp32 partials, double-atomic combine
    if (t < FI) {
        float b0 = 0.f, b1 = 0.f;
        for (int n = 0; n < CH; n += 2) {
            b0 += s[n * 21 + t];
            b1 += s[(n + 1) * 21 + t];
        }
        atomicAdd(&g_m[t], (double)(b0 + b1));
    } else if (t < FI + NPAIR) {
        int p = t - FI, i = 0;
        while (p >= FI - i) { p -= FI - i; i++; }
        int j = i + p;
        float b0 = 0.f, b1 = 0.f;
        for (int n = 0; n < CH; n += 2) {
            b0 += s[n * 21 + i] * s[n * 21 + j];
            b1 += s[(n + 1) * 21 + i] * s[(n + 1) * 21 + j];
        }
        atomicAdd(&g_G[t - FI], (double)(b0 + b1));
    }
}

// K4 (196 blocks): REDUNDANT per-block BN fold + head. No single-block kernel
// remains (R8-R10 showed grid=1 kernels cost a flat ~27us regardless of body).
__global__ void __launch_bounds__(256) k_final(
                       const float* __restrict__ W,      // gcn_W  [20,500]
                       const float* __restrict__ b,      // gcn_b  [500]
                       const float* __restrict__ gamma,  // [500]
                       const float* __restrict__ beta,   // [500]
                       const float* __restrict__ W2,     // lin_W  [500,2]
                       const float* __restrict__ lb,     // lin_b  [2]
                       float* __restrict__ out) {        // [NN*2 | 500 rsu]
    __shared__ float sW[FI * HIDD];        // 40 KB
    __shared__ float sY0[HIDD], sY1[HIDD]; // s_f*W2[f,0], s_f*W2[f,1]
    __shared__ float sGfull[FI][FI + 1];   // full symmetric Gram
    __shared__ float smm[FI];              // mean sums (fp32)
    __shared__ float sRed[40 * 6];
    __shared__ float sM[FI * NOUT];
    __shared__ float sC[NOUT];
    __shared__ float sCw[16];              // per-warp C partials
    int t = threadIdx.x;                   // 256 threads
    int bid = blockIdx.x;

    // ---- stage stats + W
    for (int k = t; k < FI * HIDD; k += 256) sW[k] = W[k];
    if (t < FI) smm[t] = (float)g_m[t];
    if (t < NPAIR) {
        int p = t, i = 0;
        while (p >= FI - i) { p -= FI - i; i++; }
        int j = i + p;
        float v = (float)g_G[t];
        sGfull[i][j] = v;
        sGfull[j][i] = v;
    }
    __syncthreads();

    // ---- fire-and-forget cleanup: last block to arrive zeroes the stats
    if (t == 0) {
        int v = atomicAdd(&g_c, 1);
        if (v == NB2 - 1) {
            for (int k = 0; k < FI; k++)    g_m[k] = 0.0;
            for (int k = 0; k < NPAIR; k++) g_G[k] = 0.0;
            g_ovfn = 0;
            g_c = 0;
        }
    }

    // ---- BN fold (every block, fp32 throughout)
    const float* a0 = (const float*)g_agg4;   // node 0 row
    float c0 = 0.f, c1 = 0.f;
    for (int f = t; f < HIDD; f += 256) {
        float w[FI];
#pragma unroll
        for (int i = 0; i < FI; i++) w[i] = sW[i * HIDD + f];
        float bf = b[f];
        float su = 0.f;
#pragma unroll
        for (int i = 0; i < FI; i++) su += smm[i] * w[i];
        float mean = (su + (float)NN * bf) * (1.f / (float)NN);
        float q = 0.f;
#pragma unroll 2
        for (int i = 0; i < FI; i++) {
            float qi = 0.f;
#pragma unroll
            for (int j = 0; j < FI; j++) qi += sGfull[i][j] * w[j];
            q += qi * w[i];
        }
        float sos = q * (1.f / (float)NN) + 2.f * bf * su * (1.f / (float)NN) + bf * bf;
        float var = sos - mean * mean;
        float sc = gamma[f] * rsqrtf(var + BN_EPS);
        float tt = beta[f] - mean * sc;
        float w20 = W2[2 * f], w21 = W2[2 * f + 1];
        sY0[f] = sc * w20;
        sY1[f] = sc * w21;
        float bst = bf * sc + tt;
        c0 += bst * w20;
        c1 += bst * w21;
        if (bid == 0) {                    // rsu_embedding (node 0)
            float u0 = 0.f;
#pragma unroll
            for (int i = 0; i < FI; i++) u0 += a0[i] * w[i];
            out[NN * NOUT + f] = (u0 + bf) * sc + tt;
        }
    }
    // C reduction: warp shuffle -> per-warp smem -> thread 0
#pragma unroll
    for (int off = 16; off > 0; off >>= 1) {
        c0 += __shfl_down_sync(0xffffffffu, c0, off);
        c1 += __shfl_down_sync(0xffffffffu, c1, off);
    }
    if ((t & 31) == 0) { sCw[(t >> 5) * 2] = c0; sCw[(t >> 5) * 2 + 1] = c1; }
    __syncthreads();
    if (t == 0) {
        float x0 = 0.f, x1 = 0.f;
#pragma unroll
        for (int k = 0; k < 8; k++) { x0 += sCw[2 * k]; x1 += sCw[2 * k + 1]; }
        sC[0] = x0 + lb[0];
        sC[1] = x1 + lb[1];
    }

    // ---- M2 fold: 40 outputs x 6 partial threads (pure LDS)
    if (t < 40 * 6) {
        int o = t / 6, part = t % 6;
        int f0 = part * 84;
        int f1 = (f0 + 84 < HIDD) ? f0 + 84 : HIDD;
        int i2 = o >> 1;
        const float* sy = (o & 1) ? sY1 : sY0;
        float acc = 0.f;
        for (int f = f0; f < f1; f++) acc += sW[i2 * HIDD + f] * sy[f];
        sRed[t] = acc;
    }
    __syncthreads();
    if (t < 40) {
        float acc = 0.f;
#pragma unroll
        for (int k = 0; k < 6; k++) acc += sRed[t * 6 + k];
        sM[t] = acc;
    }
    __syncthreads();

    // ---- head: one node per thread
    int n = bid * 256 + t;
    if (n < NN) {
        float p0 = sC[0], p1 = sC[1];
        const float4* ar = (const float4*)(g_agg4 + n * 5);
#pragma unroll
        for (int k = 0; k < 5; k++) {
            float4 v = ar[k];
            p0 += v.x * sM[(4*k+0)*NOUT] + v.y * sM[(4*k+1)*NOUT]
                + v.z * sM[(4*k+2)*NOUT] + v.w * sM[(4*k+3)*NOUT];
            p1 += v.x * sM[(4*k+0)*NOUT+1] + v.y * sM[(4*k+1)*NOUT+1]
                + v.z * sM[(4*k+2)*NOUT+1] + v.w * sM[(4*k+3)*NOUT+1];
        }
        float l0 = fmaxf(p0, 0.f), l1 = fmaxf(p1, 0.f);
        float mx = fmaxf(l0, l1);
        float e0 = expf(l0 - mx), e1 = expf(l1 - mx);
        float inv = 1.f / (e0 + e1);
        ((float2*)out)[n] = make_float2(e0 * inv, e1 * inv);
    }
}

extern "C" void kernel_launch(void* const* d_in, const int* in_sizes, int n_in,
                              void* d_out, int out_size) {
    const float* X     = (const float*)d_in[0];   // node_feature [50000,20]
    const int*   ei    = (const int*)  d_in[1];   // edge_index   [2,E]
    const float* gcnW  = (const float*)d_in[2];   // [20,500]
    const float* gcnB  = (const float*)d_in[3];   // [500]
    const float* gamma = (const float*)d_in[4];   // [500]
    const float* beta  = (const float*)d_in[5];   // [500]
    const float* linW  = (const float*)d_in[6];   // [500,2]
    const float* linB  = (const float*)d_in[7];   // [2]
    float* out = (float*)d_out;                   // [NN*2 action_prob][500 rsu]

    int E = in_sizes[1] / 2;
    int nb  = (NN + 255) / 256;
    int eb4 = (E / 4 + 255) / 256 + 1;

    k_build<<<eb4, 256>>>(ei, E);
    k_prepX<<<nb, 256>>>(X);
    k_gather<<<NB, 256>>>(0.f);
    k_final<<<NB2, 256>>>(gcnW, gcnB, gamma, beta, linW, linB, out);
}

// round 12
// speedup vs baseline: 1.2095x; 1.1416x over previous
#include <cuda_runtime.h>
#include <math.h>

#define NN    50000
#define FI    20
#define HIDD  500
#define NOUT  2
#define NPAIR 210            // upper-triangular (incl. diag) pairs of 20
#define BN_EPS 1e-5f
#define CH    250            // nodes per block in gather/stats (200 blocks)
#define NB    (NN / CH)
#define NB2   196            // k_final blocks: 196*256 >= 50000
#define PAD   64             // padded-CSR width (deg ~ Poisson(16))
#define OVFC  4096           // overflow capacity (general-correctness fallback)

// ---- scratch (__device__ globals, zero-initialized; self-cleaning) ----
static __device__ int            g_cnt[NN];        // degree counter (build), zeroed in gather
static __device__ unsigned short g_slots[PAD * NN];// slot-major CSR: slots[j*NN+c]=row
static __device__ int            g_ovfn;           // overflow count (zeroed by last block)
static __device__ int2           g_ovf[OVFC];      // overflow (row,col) pairs
static __device__ float          g_dinv[NN];
static __device__ float4         g_Xs4[NN * 5];    // Xs = dinv[n] * X[n]
static __device__ float4         g_agg4[NN * 5];   // aggX = dinv * (sum + Xs)
static __device__ double         g_m[FI];          // column sums of aggX
static __device__ double         g_G[NPAIR];       // upper-tri Gram aggX^T aggX
static __device__ int            g_c;              // gather arrival counter
static __device__ float          g_M2[FI * NOUT];  // folded 20x2 head matrix (per-call)
static __device__ float          g_C[NOUT];        // folded bias (per-call)

// K1: build padded CSR: for edge (r,c): slots[pos][c] = r  (int atomics only)
__global__ void __launch_bounds__(256) k_build(const int* __restrict__ ei, int E) {
    int t = blockIdx.x * blockDim.x + threadIdx.x;
    int e = 4 * t;
    if (e + 3 < E) {
        int4 r4 = *(const int4*)(ei + e);
        int4 c4 = *(const int4*)(ei + E + e);
        int rr[4] = {r4.x, r4.y, r4.z, r4.w};
        int cc[4] = {c4.x, c4.y, c4.z, c4.w};
#pragma unroll
        for (int k = 0; k < 4; k++) {
            int pos = atomicAdd(&g_cnt[cc[k]], 1);
            if (pos < PAD) g_slots[pos * NN + cc[k]] = (unsigned short)rr[k];
            else {
                int o = atomicAdd(&g_ovfn, 1);
                if (o < OVFC) g_ovf[o] = make_int2(rr[k], cc[k]);
            }
        }
    } else {
        for (int k = e; k < E; k++) {
            int r = ei[k], c = ei[E + k];
            int pos = atomicAdd(&g_cnt[c], 1);
            if (pos < PAD) g_slots[pos * NN + c] = (unsigned short)r;
            else {
                int o = atomicAdd(&g_ovfn, 1);
                if (o < OVFC) g_ovf[o] = make_int2(r, c);
            }
        }
    }
}

// K2: dinv = rsqrt(deg+1); Xs[n] = dinv[n]*X[n]  (keeps g_cnt for gather)
__global__ void __launch_bounds__(256) k_prepX(const float* __restrict__ X) {
    int n = blockIdx.x * blockDim.x + threadIdx.x;
    if (n >= NN) return;
    float d = rsqrtf((float)(g_cnt[n] + 1));
    g_dinv[n] = d;
    const float4* xr = (const float4*)(X + n * FI);
#pragma unroll
    for (int k = 0; k < 5; k++) {
        float4 v = xr[k];
        v.x *= d; v.y *= d; v.z *= d; v.w *= d;
        g_Xs4[n * 5 + k] = v;
    }
}

// K3: gather + stats; the LAST-ARRIVING block additionally computes the BN
//     fold -> g_M2/g_C/rsu (nobody waits for it). Self-cleans all state.
__global__ void __launch_bounds__(256) k_gather(
                       const float* __restrict__ W,      // gcn_W  [20,500]
                       const float* __restrict__ b,      // gcn_b  [500]
                       const float* __restrict__ gamma,  // [500]
                       const float* __restrict__ beta,   // [500]
                       const float* __restrict__ W2,     // lin_W  [500,2]
                       const float* __restrict__ lb,     // lin_b  [2]
                       float* __restrict__ out) {        // [NN*2 | 500 rsu]
    __shared__ float s[CH * 21];               // stride 21: conflict-free
    __shared__ int   isLast;
    __shared__ float smm[FI];
    __shared__ float sGfull[FI][FI + 1];
    __shared__ float sRed[8][42];              // per-warp fold partials
    int t = threadIdx.x;                       // 256 threads (250 gather)
    int n0 = blockIdx.x * CH;
    int ovfn = g_ovfn;                         // 0 on this input

    if (t < CH) {
        int n = n0 + t;
        int deg = g_cnt[n];
        g_cnt[n] = 0;                          // self-clean for next replay
        float4 a0 = make_float4(0.f,0.f,0.f,0.f), a1 = a0, a2 = a0, a3 = a0, a4 = a0;
        int m = deg < PAD ? deg : PAD;
        for (int j = 0; j < m; j++) {
            int r = (int)g_slots[j * NN + n];  // coalesced across threads
            const float4* xs = g_Xs4 + r * 5;
            float4 v0 = __ldg(xs + 0), v1 = __ldg(xs + 1), v2 = __ldg(xs + 2),
                   v3 = __ldg(xs + 3), v4 = __ldg(xs + 4);
            a0.x += v0.x; a0.y += v0.y; a0.z += v0.z; a0.w += v0.w;
            a1.x += v1.x; a1.y += v1.y; a1.z += v1.z; a1.w += v1.w;
            a2.x += v2.x; a2.y += v2.y; a2.z += v2.z; a2.w += v2.w;
            a3.x += v3.x; a3.y += v3.y; a3.z += v3.z; a3.w += v3.w;
            a4.x += v4.x; a4.y += v4.y; a4.z += v4.z; a4.w += v4.w;
        }
        if (ovfn > 0) {                        // rare general-correctness path
            int L = ovfn < OVFC ? ovfn : OVFC;
            for (int o = 0; o < L; o++) {
                int2 rc = g_ovf[o];
                if (rc.y == n) {
                    const float4* xs = g_Xs4 + rc.x * 5;
                    float4 v0 = xs[0], v1 = xs[1], v2 = xs[2], v3 = xs[3], v4 = xs[4];
                    a0.x += v0.x; a0.y += v0.y; a0.z += v0.z; a0.w += v0.w;
                    a1.x += v1.x; a1.y += v1.y; a1.z += v1.z; a1.w += v1.w;
                    a2.x += v2.x; a2.y += v2.y; a2.z += v2.z; a2.w += v2.w;
                    a3.x += v3.x; a3.y += v3.y; a3.z += v3.z; a3.w += v3.w;
                    a4.x += v4.x; a4.y += v4.y; a4.z += v4.z; a4.w += v4.w;
                }
            }
        }
        float d = g_dinv[n];
        const float4* xsn = g_Xs4 + n * 5;
        float4 w0 = xsn[0], w1 = xsn[1], w2 = xsn[2], w3 = xsn[3], w4 = xsn[4];
        a0.x = d*(a0.x+w0.x); a0.y = d*(a0.y+w0.y); a0.z = d*(a0.z+w0.z); a0.w = d*(a0.w+w0.w);
        a1.x = d*(a1.x+w1.x); a1.y = d*(a1.y+w1.y); a1.z = d*(a1.z+w1.z); a1.w = d*(a1.w+w1.w);
        a2.x = d*(a2.x+w2.x); a2.y = d*(a2.y+w2.y); a2.z = d*(a2.z+w2.z); a2.w = d*(a2.w+w2.w);
        a3.x = d*(a3.x+w3.x); a3.y = d*(a3.y+w3.y); a3.z = d*(a3.z+w3.z); a3.w = d*(a3.w+w3.w);
        a4.x = d*(a4.x+w4.x); a4.y = d*(a4.y+w4.y); a4.z = d*(a4.z+w4.z); a4.w = d*(a4.w+w4.w);
        float4* ag = g_agg4 + n * 5;
        ag[0] = a0; ag[1] = a1; ag[2] = a2; ag[3] = a3; ag[4] = a4;
        float* sr = s + t * 21;
        sr[0]=a0.x; sr[1]=a0.y; sr[2]=a0.z; sr[3]=a0.w;
        sr[4]=a1.x; sr[5]=a1.y; sr[6]=a1.z; sr[7]=a1.w;
        sr[8]=a2.x; sr[9]=a2.y; sr[10]=a2.z; sr[11]=a2.w;
        sr[12]=a3.x; sr[13]=a3.y; sr[14]=a3.z; sr[15]=a3.w;
        sr[16]=a4.x; sr[17]=a4.y; sr[18]=a4.z; sr[19]=a4.w;
    }
    __syncthreads();

    // stats: fp32 partials, double-atomic combine
    if (t < FI) {
        float b0 = 0.f, b1 = 0.f;
        for (int n = 0; n < CH; n += 2) {
            b0 += s[n * 21 + t];
            b1 += s[(n + 1) * 21 + t];
        }
        atomicAdd(&g_m[t], (double)(b0 + b1));
    } else if (t < FI + NPAIR) {
        int p = t - FI, i = 0;
        while (p >= FI - i) { p -= FI - i; i++; }
        int j = i + p;
        float b0 = 0.f, b1 = 0.f;
        for (int n = 0; n < CH; n += 2) {
            b0 += s[n * 21 + i] * s[n * 21 + j];
            b1 += s[(n + 1) * 21 + i] * s[(n + 1) * 21 + j];
        }
        atomicAdd(&g_G[t - FI], (double)(b0 + b1));
    }
    __threadfence();                   // make this thread's atomics visible
    __syncthreads();

    // ---- last-block election (nobody waits on this)
    if (t == 0) isLast = (atomicAdd(&g_c, 1) == NB - 1);
    __syncthreads();
    if (!isLast) return;
    __threadfence();                   // all 200 blocks' stats now visible

    // ---- stage complete stats; self-clean
    if (t < FI) { smm[t] = (float)g_m[t]; g_m[t] = 0.0; }
    if (t < NPAIR) {
        int p = t, i = 0;
        while (p >= FI - i) { p -= FI - i; i++; }
        int j = i + p;
        float v = (float)g_G[t];
        g_G[t] = 0.0;
        sGfull[i][j] = v;
        sGfull[j][i] = v;
    }
    if (t == 0) { g_c = 0; g_ovfn = 0; }
    __syncthreads();

    // ---- fold: per-feature BN; M2 accumulated in registers from w[20]
    float a0row[FI];                   // node 0 aggX row (rsu)
#pragma unroll
    for (int i = 0; i < FI; i++) a0row[i] = ((const float*)g_agg4)[i];
    float m2loc[FI * NOUT];
#pragma unroll
    for (int k = 0; k < FI * NOUT; k++) m2loc[k] = 0.f;
    float c0 = 0.f, c1 = 0.f;
    for (int f = t; f < HIDD; f += 256) {
        float w[FI];
#pragma unroll
        for (int i = 0; i < FI; i++) w[i] = W[i * HIDD + f];
        float bf = b[f];
        float su = 0.f;
#pragma unroll
        for (int i = 0; i < FI; i++) su += smm[i] * w[i];
        float mean = (su + (float)NN * bf) * (1.f / (float)NN);
        float q = 0.f;
#pragma unroll 2
        for (int i = 0; i < FI; i++) {
            float qi = 0.f;
#pragma unroll
            for (int j = 0; j < FI; j++) qi += sGfull[i][j] * w[j];
            q += qi * w[i];
        }
        float sos = q * (1.f / (float)NN) + 2.f * bf * su * (1.f / (float)NN) + bf * bf;
        float var = sos - mean * mean;
        float sc = gamma[f] * rsqrtf(var + BN_EPS);
        float tt = beta[f] - mean * sc;
        float w20 = W2[2 * f], w21 = W2[2 * f + 1];
        float y0 = sc * w20, y1 = sc * w21;
#pragma unroll
        for (int i = 0; i < FI; i++) {
            m2loc[2 * i]     += w[i] * y0;
            m2loc[2 * i + 1] += w[i] * y1;
        }
        float bst = bf * sc + tt;
        c0 += bst * w20;
        c1 += bst * w21;
        float u0 = 0.f;                // rsu_embedding (node 0)
#pragma unroll
        for (int i = 0; i < FI; i++) u0 += a0row[i] * w[i];
        out[NN * NOUT + f] = (u0 + bf) * sc + tt;
    }
    // ---- block reduction of m2loc[40], c0, c1
#pragma unroll
    for (int off = 16; off > 0; off >>= 1) {
#pragma unroll
        for (int k = 0; k < FI * NOUT; k++)
            m2loc[k] += __shfl_down_sync(0xffffffffu, m2loc[k], off);
        c0 += __shfl_down_sync(0xffffffffu, c0, off);
        c1 += __shfl_down_sync(0xffffffffu, c1, off);
    }
    if ((t & 31) == 0) {
        int wid = t >> 5;
#pragma unroll
        for (int k = 0; k < FI * NOUT; k++) sRed[wid][k] = m2loc[k];
        sRed[wid][40] = c0;
        sRed[wid][41] = c1;
    }
    __syncthreads();
    if (t < 42) {
        float acc = 0.f;
#pragma unroll
        for (int k = 0; k < 8; k++) acc += sRed[k][t];
        if (t < FI * NOUT) g_M2[t] = acc;
        else               g_C[t - FI * NOUT] = acc + lb[t - FI * NOUT];
    }
}

// K4: slim head: logits = relu(aggX[n].M2 + C); softmax over 2 classes
__global__ void __launch_bounds__(256) k_final(float* __restrict__ out) {
    __shared__ float sM[FI * NOUT];
    __shared__ float sC[NOUT];
    int t = threadIdx.x;
    if (t < FI * NOUT) sM[t] = g_M2[t];
    if (t < NOUT)      sC[t] = g_C[t];
    __syncthreads();
    int n = blockIdx.x * 256 + t;
    if (n >= NN) return;
    float p0 = sC[0], p1 = sC[1];
    const float4* ar = (const float4*)(g_agg4 + n * 5);
#pragma unroll
    for (int k = 0; k < 5; k++) {
        float4 v = ar[k];
        p0 += v.x * sM[(4*k+0)*NOUT] + v.y * sM[(4*k+1)*NOUT]
            + v.z * sM[(4*k+2)*NOUT] + v.w * sM[(4*k+3)*NOUT];
        p1 += v.x * sM[(4*k+0)*NOUT+1] + v.y * sM[(4*k+1)*NOUT+1]
            + v.z * sM[(4*k+2)*NOUT+1] + v.w * sM[(4*k+3)*NOUT+1];
    }
    float l0 = fmaxf(p0, 0.f), l1 = fmaxf(p1, 0.f);
    float mx = fmaxf(l0, l1);
    float e0 = expf(l0 - mx), e1 = expf(l1 - mx);
    float inv = 1.f / (e0 + e1);
    ((float2*)out)[n] = make_float2(e0 * inv, e1 * inv);
}

extern "C" void kernel_launch(void* const* d_in, const int* in_sizes, int n_in,
                              void* d_out, int out_size) {
    const float* X     = (const float*)d_in[0];   // node_feature [50000,20]
    const int*   ei    = (const int*)  d_in[1];   // edge_index   [2,E]
    const float* gcnW  = (const float*)d_in[2];   // [20,500]
    const float* gcnB  = (const float*)d_in[3];   // [500]
    const float* gamma = (const float*)d_in[4];   // [500]
    const float* beta  = (const float*)d_in[5];   // [500]
    const float* linW  = (const float*)d_in[6];   // [500,2]
    const float* linB  = (const float*)d_in[7];   // [2]
    float* out = (float*)d_out;                   // [NN*2 action_prob][500 rsu]

    int E = in_sizes[1] / 2;
    int nb  = (NN + 255) / 256;
    int eb4 = (E / 4 + 255) / 256 + 1;

    k_build<<<eb4, 256>>>(ei, E);
    k_prepX<<<nb, 256>>>(X);
    k_gather<<<NB, 256>>>(gcnW, gcnB, gamma, beta, linW, linB, out);
    k_final<<<NB2, 256>>>(out);
}

// round 13
// speedup vs baseline: 1.2164x; 1.0057x over previous
#include <cuda_runtime.h>
#include <math.h>

#define NN    50000
#define FI    20
#define HIDD  500
#define NOUT  2
#define NPAIR 210            // upper-triangular (incl. diag) pairs of 20
#define BN_EPS 1e-5f
#define CH    250            // nodes per block in gather/stats (200 blocks)
#define NB    (NN / CH)
#define NB2   196            // k_final blocks: 196*256 >= 50000
#define PAD   64             // padded-CSR width (deg ~ Poisson(16))
#define OVFC  4096           // overflow capacity (general-correctness fallback)

// ---- scratch (__device__ globals, zero-initialized; self-cleaning) ----
static __device__ int            g_cnt[NN];        // degree counts (zeroed in k_final)
static __device__ unsigned short g_slots[PAD * NN];// slot-major CSR: slots[j*NN+c]=row
static __device__ int            g_ovfn;           // overflow count (zeroed by last gather block)
static __device__ int2           g_ovf[OVFC];      // overflow (row,col) pairs
static __device__ float4         g_agg4[NN * 5];   // aggX = dinv_c*(sum + Xs_c)
static __device__ double         g_m[FI];          // column sums of aggX
static __device__ double         g_G[NPAIR];       // upper-tri Gram aggX^T aggX
static __device__ int            g_c;              // gather arrival counter
static __device__ float          g_M2[FI * NOUT];  // folded 20x2 head matrix
static __device__ float          g_C[NOUT];        // folded bias

// K1: build padded CSR: for edge (r,c): slots[pos][c] = r  (int atomics only)
__global__ void __launch_bounds__(256) k_build(const int* __restrict__ ei, int E) {
    int t = blockIdx.x * blockDim.x + threadIdx.x;
    int e = 4 * t;
    if (e + 3 < E) {
        int4 r4 = *(const int4*)(ei + e);
        int4 c4 = *(const int4*)(ei + E + e);
        int rr[4] = {r4.x, r4.y, r4.z, r4.w};
        int cc[4] = {c4.x, c4.y, c4.z, c4.w};
#pragma unroll
        for (int k = 0; k < 4; k++) {
            int pos = atomicAdd(&g_cnt[cc[k]], 1);
            if (pos < PAD) g_slots[pos * NN + cc[k]] = (unsigned short)rr[k];
            else {
                int o = atomicAdd(&g_ovfn, 1);
                if (o < OVFC) g_ovf[o] = make_int2(rr[k], cc[k]);
            }
        }
    } else {
        for (int k = e; k < E; k++) {
            int r = ei[k], c = ei[E + k];
            int pos = atomicAdd(&g_cnt[c], 1);
            if (pos < PAD) g_slots[pos * NN + c] = (unsigned short)r;
            else {
                int o = atomicAdd(&g_ovfn, 1);
                if (o < OVFC) g_ovf[o] = make_int2(r, c);
            }
        }
    }
}

// K2: gather straight from X (dinv computed inline from counts; no Xs array),
//     stats, and last-arriving-block BN fold -> g_M2/g_C/rsu. MLP x2 unroll.
__global__ void __launch_bounds__(256) k_gather(
                       const float* __restrict__ X,      // node_feature [NN,20]
                       const float* __restrict__ W,      // gcn_W  [20,500]
                       const float* __restrict__ b,      // gcn_b  [500]
                       const float* __restrict__ gamma,  // [500]
                       const float* __restrict__ beta,   // [500]
                       const float* __restrict__ W2,     // lin_W  [500,2]
                       const float* __restrict__ lb,     // lin_b  [2]
                       float* __restrict__ out) {        // [NN*2 | 500 rsu]
    __shared__ float s[CH * 21];               // stride 21: conflict-free
    __shared__ int   isLast;
    __shared__ float smm[FI];
    __shared__ float sGfull[FI][FI + 1];
    __shared__ float sRed[8][42];              // per-warp fold partials
    int t = threadIdx.x;                       // 256 threads (250 gather)
    int n0 = blockIdx.x * CH;
    int ovfn = g_ovfn;                         // 0 on this input

    if (t < CH) {
        int n = n0 + t;
        int deg = g_cnt[n];                    // NOT zeroed here (k_final cleans)
        float4 a0 = make_float4(0.f,0.f,0.f,0.f), a1 = a0, a2 = a0, a3 = a0, a4 = a0;
        int m = deg < PAD ? deg : PAD;
        int j = 0;
        for (; j + 1 < m; j += 2) {            // MLP x2: two independent chains
            int r1 = (int)g_slots[j * NN + n];
            int r2 = (int)g_slots[(j + 1) * NN + n];
            float d1 = rsqrtf((float)(g_cnt[r1] + 1));
            float d2 = rsqrtf((float)(g_cnt[r2] + 1));
            const float4* x1 = (const float4*)(X + r1 * FI);
            const float4* x2 = (const float4*)(X + r2 * FI);
            float4 u0 = __ldg(x1+0), u1 = __ldg(x1+1), u2 = __ldg(x1+2),
                   u3 = __ldg(x1+3), u4 = __ldg(x1+4);
            float4 v0 = __ldg(x2+0), v1 = __ldg(x2+1), v2 = __ldg(x2+2),
                   v3 = __ldg(x2+3), v4 = __ldg(x2+4);
            a0.x += d1*u0.x + d2*v0.x; a0.y += d1*u0.y + d2*v0.y;
            a0.z += d1*u0.z + d2*v0.z; a0.w += d1*u0.w + d2*v0.w;
            a1.x += d1*u1.x + d2*v1.x; a1.y += d1*u1.y + d2*v1.y;
            a1.z += d1*u1.z + d2*v1.z; a1.w += d1*u1.w + d2*v1.w;
            a2.x += d1*u2.x + d2*v2.x; a2.y += d1*u2.y + d2*v2.y;
            a2.z += d1*u2.z + d2*v2.z; a2.w += d1*u2.w + d2*v2.w;
            a3.x += d1*u3.x + d2*v3.x; a3.y += d1*u3.y + d2*v3.y;
            a3.z += d1*u3.z + d2*v3.z; a3.w += d1*u3.w + d2*v3.w;
            a4.x += d1*u4.x + d2*v4.x; a4.y += d1*u4.y + d2*v4.y;
            a4.z += d1*u4.z + d2*v4.z; a4.w += d1*u4.w + d2*v4.w;
        }
        if (j < m) {
            int r1 = (int)g_slots[j * NN + n];
            float d1 = rsqrtf((float)(g_cnt[r1] + 1));
            const float4* x1 = (const float4*)(X + r1 * FI);
            float4 u0 = __ldg(x1+0), u1 = __ldg(x1+1), u2 = __ldg(x1+2),
                   u3 = __ldg(x1+3), u4 = __ldg(x1+4);
            a0.x += d1*u0.x; a0.y += d1*u0.y; a0.z += d1*u0.z; a0.w += d1*u0.w;
            a1.x += d1*u1.x; a1.y += d1*u1.y; a1.z += d1*u1.z; a1.w += d1*u1.w;
            a2.x += d1*u2.x; a2.y += d1*u2.y; a2.z += d1*u2.z; a2.w += d1*u2.w;
            a3.x += d1*u3.x; a3.y += d1*u3.y; a3.z += d1*u3.z; a3.w += d1*u3.w;
            a4.x += d1*u4.x; a4.y += d1*u4.y; a4.z += d1*u4.z; a4.w += d1*u4.w;
        }
        if (ovfn > 0) {                        // rare general-correctness path
            int L = ovfn < OVFC ? ovfn : OVFC;
            for (int o = 0; o < L; o++) {
                int2 rc = g_ovf[o];
                if (rc.y == n) {
                    float dr = rsqrtf((float)(g_cnt[rc.x] + 1));
                    const float4* x1 = (const float4*)(X + rc.x * FI);
                    float4 u0 = x1[0], u1 = x1[1], u2 = x1[2], u3 = x1[3], u4 = x1[4];
                    a0.x += dr*u0.x; a0.y += dr*u0.y; a0.z += dr*u0.z; a0.w += dr*u0.w;
                    a1.x += dr*u1.x; a1.y += dr*u1.y; a1.z += dr*u1.z; a1.w += dr*u1.w;
                    a2.x += dr*u2.x; a2.y += dr*u2.y; a2.z += dr*u2.z; a2.w += dr*u2.w;
                    a3.x += dr*u3.x; a3.y += dr*u3.y; a3.z += dr*u3.z; a3.w += dr*u3.w;
                    a4.x += dr*u4.x; a4.y += dr*u4.y; a4.z += dr*u4.z; a4.w += dr*u4.w;
                }
            }
        }
        // self term + outer dinv scaling
        float d = rsqrtf((float)(deg + 1));
        const float4* xn = (const float4*)(X + n * FI);
        float4 w0 = xn[0], w1 = xn[1], w2 = xn[2], w3 = xn[3], w4 = xn[4];
        a0.x = d*(a0.x + d*w0.x); a0.y = d*(a0.y + d*w0.y);
        a0.z = d*(a0.z + d*w0.z); a0.w = d*(a0.w + d*w0.w);
        a1.x = d*(a1.x + d*w1.x); a1.y = d*(a1.y + d*w1.y);
        a1.z = d*(a1.z + d*w1.z); a1.w = d*(a1.w + d*w1.w);
        a2.x = d*(a2.x + d*w2.x); a2.y = d*(a2.y + d*w2.y);
        a2.z = d*(a2.z + d*w2.z); a2.w = d*(a2.w + d*w2.w);
        a3.x = d*(a3.x + d*w3.x); a3.y = d*(a3.y + d*w3.y);
        a3.z = d*(a3.z + d*w3.z); a3.w = d*(a3.w + d*w3.w);
        a4.x = d*(a4.x + d*w4.x); a4.y = d*(a4.y + d*w4.y);
        a4.z = d*(a4.z + d*w4.z); a4.w = d*(a4.w + d*w4.w);
        float4* ag = g_agg4 + n * 5;
        ag[0] = a0; ag[1] = a1; ag[2] = a2; ag[3] = a3; ag[4] = a4;
        float* sr = s + t * 21;
        sr[0]=a0.x; sr[1]=a0.y; sr[2]=a0.z; sr[3]=a0.w;
        sr[4]=a1.x; sr[5]=a1.y; sr[6]=a1.z; sr[7]=a1.w;
        sr[8]=a2.x; sr[9]=a2.y; sr[10]=a2.z; sr[11]=a2.w;
        sr[12]=a3.x; sr[13]=a3.y; sr[14]=a3.z; sr[15]=a3.w;
        sr[16]=a4.x; sr[17]=a4.y; sr[18]=a4.z; sr[19]=a4.w;
    }
    __syncthreads();

    // stats: fp32 partials, double-atomic combine
    if (t < FI) {
        float b0 = 0.f, b1 = 0.f;
        for (int n = 0; n < CH; n += 2) {
            b0 += s[n * 21 + t];
            b1 += s[(n + 1) * 21 + t];
        }
        atomicAdd(&g_m[t], (double)(b0 + b1));
    } else if (t < FI + NPAIR) {
        int p = t - FI, i = 0;
        while (p >= FI - i) { p -= FI - i; i++; }
        int j2 = i + p;
        float b0 = 0.f, b1 = 0.f;
        for (int n = 0; n < CH; n += 2) {
            b0 += s[n * 21 + i] * s[n * 21 + j2];
            b1 += s[(n + 1) * 21 + i] * s[(n + 1) * 21 + j2];
        }
        atomicAdd(&g_G[t - FI], (double)(b0 + b1));
    }
    __threadfence();
    __syncthreads();

    // ---- last-block election (nobody waits on this)
    if (t == 0) isLast = (atomicAdd(&g_c, 1) == NB - 1);
    __syncthreads();
    if (!isLast) return;
    __threadfence();                   // all blocks' stats now visible

    // ---- stage complete stats; self-clean
    if (t < FI) { smm[t] = (float)g_m[t]; g_m[t] = 0.0; }
    if (t < NPAIR) {
        int p = t, i = 0;
        while (p >= FI - i) { p -= FI - i; i++; }
        int j2 = i + p;
        float v = (float)g_G[t];
        g_G[t] = 0.0;
        sGfull[i][j2] = v;
        sGfull[j2][i] = v;
    }
    if (t == 0) { g_c = 0; g_ovfn = 0; }
    __syncthreads();

    // ---- fold: per-feature BN; M2 accumulated in registers from w[20]
    float a0row[FI];
#pragma unroll
    for (int i = 0; i < FI; i++) a0row[i] = ((const float*)g_agg4)[i];
    float m2loc[FI * NOUT];
#pragma unroll
    for (int k = 0; k < FI * NOUT; k++) m2loc[k] = 0.f;
    float c0 = 0.f, c1 = 0.f;
    for (int f = t; f < HIDD; f += 256) {
        float w[FI];
#pragma unroll
        for (int i = 0; i < FI; i++) w[i] = W[i * HIDD + f];
        float bf = b[f];
        float su = 0.f;
#pragma unroll
        for (int i = 0; i < FI; i++) su += smm[i] * w[i];
        float mean = (su + (float)NN * bf) * (1.f / (float)NN);
        float q = 0.f;
#pragma unroll 2
        for (int i = 0; i < FI; i++) {
            float qi = 0.f;
#pragma unroll
            for (int j2 = 0; j2 < FI; j2++) qi += sGfull[i][j2] * w[j2];
            q += qi * w[i];
        }
        float sos = q * (1.f / (float)NN) + 2.f * bf * su * (1.f / (float)NN) + bf * bf;
        float var = sos - mean * mean;
        float sc = gamma[f] * rsqrtf(var + BN_EPS);
        float tt = beta[f] - mean * sc;
        float w20 = W2[2 * f], w21 = W2[2 * f + 1];
        float y0 = sc * w20, y1 = sc * w21;
#pragma unroll
        for (int i = 0; i < FI; i++) {
            m2loc[2 * i]     += w[i] * y0;
            m2loc[2 * i + 1] += w[i] * y1;
        }
        float bst = bf * sc + tt;
        c0 += bst * w20;
        c1 += bst * w21;
        float u0 = 0.f;                // rsu_embedding (node 0)
#pragma unroll
        for (int i = 0; i < FI; i++) u0 += a0row[i] * w[i];
        out[NN * NOUT + f] = (u0 + bf) * sc + tt;
    }
#pragma unroll
    for (int off = 16; off > 0; off >>= 1) {
#pragma unroll
        for (int k = 0; k < FI * NOUT; k++)
            m2loc[k] += __shfl_down_sync(0xffffffffu, m2loc[k], off);
        c0 += __shfl_down_sync(0xffffffffu, c0, off);
        c1 += __shfl_down_sync(0xffffffffu, c1, off);
    }
    if ((t & 31) == 0) {
        int wid = t >> 5;
#pragma unroll
        for (int k = 0; k < FI * NOUT; k++) sRed[wid][k] = m2loc[k];
        sRed[wid][40] = c0;
        sRed[wid][41] = c1;
    }
    __syncthreads();
    if (t < 42) {
        float acc = 0.f;
#pragma unroll
        for (int k = 0; k < 8; k++) acc += sRed[k][t];
        if (t < FI * NOUT) g_M2[t] = acc;
        else               g_C[t - FI * NOUT] = acc + lb[t - FI * NOUT];
    }
}

// K3: slim head + g_cnt cleanup (covers all nodes; build needs zeros next call)
__global__ void __launch_bounds__(256) k_final(float* __restrict__ out) {
    __shared__ float sM[FI * NOUT];
    __shared__ float sC[NOUT];
    int t = threadIdx.x;
    if (t < FI * NOUT) sM[t] = g_M2[t];
    if (t < NOUT)      sC[t] = g_C[t];
    __syncthreads();
    int n = blockIdx.x * 256 + t;
    if (n >= NN) return;
    g_cnt[n] = 0;                              // self-clean for next replay
    float p0 = sC[0], p1 = sC[1];
    const float4* ar = (const float4*)(g_agg4 + n * 5);
#pragma unroll
    for (int k = 0; k < 5; k++) {
        float4 v = ar[k];
        p0 += v.x * sM[(4*k+0)*NOUT] + v.y * sM[(4*k+1)*NOUT]
            + v.z * sM[(4*k+2)*NOUT] + v.w * sM[(4*k+3)*NOUT];
        p1 += v.x * sM[(4*k+0)*NOUT+1] + v.y * sM[(4*k+1)*NOUT+1]
            + v.z * sM[(4*k+2)*NOUT+1] + v.w * sM[(4*k+3)*NOUT+1];
    }
    float l0 = fmaxf(p0, 0.f), l1 = fmaxf(p1, 0.f);
    float mx = fmaxf(l0, l1);
    float e0 = expf(l0 - mx), e1 = expf(l1 - mx);
    float inv = 1.f / (e0 + e1);
    ((float2*)out)[n] = make_float2(e0 * inv, e1 * inv);
}

extern "C" void kernel_launch(void* const* d_in, const int* in_sizes, int n_in,
                              void* d_out, int out_size) {
    const float* X     = (const float*)d_in[0];   // node_feature [50000,20]
    const int*   ei    = (const int*)  d_in[1];   // edge_index   [2,E]
    const float* gcnW  = (const float*)d_in[2];   // [20,500]
    const float* gcnB  = (const float*)d_in[3];   // [500]
    const float* gamma = (const float*)d_in[4];   // [500]
    const float* beta  = (const float*)d_in[5];   // [500]
    const float* linW  = (const float*)d_in[6];   // [500,2]
    const float* linB  = (const float*)d_in[7];   // [2]
    float* out = (float*)d_out;                   // [NN*2 action_prob][500 rsu]

    int E = in_sizes[1] / 2;
    int eb4 = (E / 4 + 255) / 256 + 1;

    k_build<<<eb4, 256>>>(ei, E);
    k_gather<<<NB, 256>>>(X, gcnW, gcnB, gamma, beta, linW, linB, out);
    k_final<<<NB2, 256>>>(out);
}